// round 10
// baseline (speedup 1.0000x reference)
#include <cuda_runtime.h>
#include <cuda_fp16.h>
#include <math.h>
#include <stdint.h>

// ---------------------------------------------------------------------------
// TimeMix (RWKV-style): B=4, S=4096, D=2048 — fp16 mma.sync.
// Round 10: revert mainloop to round-8; hybrid launch co-schedules the
// r-projection GEMM (tensor-bound) with scan_partial (HBM-bound).
// ---------------------------------------------------------------------------

namespace {
constexpr int kB = 4;
constexpr int kS = 4096;
constexpr int kD = 2048;
constexpr int kM = kB * kS;          // 16384
constexpr int kChunks = 64;
constexpr int kCLen = kS / kChunks;  // 64

constexpr int BM = 128, BN = 128, BKH = 64;  // BKH halves = 128 B rows
constexpr int NTHR = 128;                    // 4 warps, 2x2 of 64x64
constexpr int KSTAGES = kD / BKH;            // 32
constexpr uint32_t A_BYTES = BM * 128;       // 16384
constexpr uint32_t STAGE_BYTES = 2 * A_BYTES;     // 32768
constexpr uint32_t SMEM_BYTES = 3 * STAGE_BYTES;  // 98304
constexpr int NTILES = kD / BN;              // 16
}  // namespace

// Scratch (device globals; allocation APIs forbidden)
__device__ float g_w[kM * kD];
__device__ float g_k[kM * kD];
__device__ __align__(16) __half g_rh[kM * kD];
__device__ __align__(16) __half g_vh[kM * kD];
__device__ float g_cnum[kChunks * kB * kD];
__device__ float g_cden[kChunks * kB * kD];
__device__ float g_inum[kChunks * kB * kD];
__device__ float g_iden[kChunks * kB * kD];
__device__ __align__(16) __half g_xh[kM * kD];
__device__ __align__(16) __half g_yh[kM * kD];
__device__ __align__(16) __half g_wh[5][kD * kD];

// ------------------------------- asm helpers -------------------------------
__device__ __forceinline__ uint32_t smem_u32(const void* p) {
  uint32_t a;
  asm("{ .reg .u64 t; cvta.to.shared.u64 t, %1; cvt.u32.u64 %0, t; }"
      : "=r"(a) : "l"(p));
  return a;
}
__device__ __forceinline__ void cp16(uint32_t dst, const void* src) {
  asm volatile("cp.async.cg.shared.global [%0], [%1], 16;" :: "r"(dst), "l"(src));
}
#define CP_COMMIT() asm volatile("cp.async.commit_group;" ::: "memory")
#define CP_WAIT1() asm volatile("cp.async.wait_group 1;" ::: "memory")

#define LDM_X4(r0, r1, r2, r3, addr)                                           \
  asm volatile("ldmatrix.sync.aligned.m8n8.x4.shared.b16 {%0,%1,%2,%3}, [%4];" \
               : "=r"(r0), "=r"(r1), "=r"(r2), "=r"(r3) : "r"(addr))

#define MMA16816(d, a, b)                                                   \
  asm volatile(                                                             \
      "mma.sync.aligned.m16n8k16.row.col.f32.f16.f16.f32 "                  \
      "{%0,%1,%2,%3}, {%4,%5,%6,%7}, {%8,%9}, {%0,%1,%2,%3};"               \
      : "+f"(d[0]), "+f"(d[1]), "+f"(d[2]), "+f"(d[3])                      \
      : "r"(a[0]), "r"(a[1]), "r"(a[2]), "r"(a[3]), "r"(b[0]), "r"(b[1]))

__device__ __forceinline__ uint32_t swz(uint32_t off) {
  return off ^ ((off >> 3) & 0x70);
}

// Fill one stage: A tile 128 x 128B, B tile 128 x 128B. K-major, SW128.
__device__ __forceinline__ void stage_fill(uint32_t slotbase, const __half* A,
                                           const __half* W, int mBase,
                                           int nBase, int k0, int tid) {
#pragma unroll
  for (int t = 0; t < 16; t++) {
    const int idx = tid + t * NTHR;     // 0..2047
    const int row = (idx & 1023) >> 3;  // 0..127
    const int j = idx & 7;              // 16B chunk in row
    const __half* src;
    uint32_t dstBase;
    if (idx < 1024) {
      src = A + (size_t)(mBase + row) * kD;
      dstBase = slotbase;
    } else {
      src = W + (size_t)(nBase + row) * kD;
      dstBase = slotbase + A_BYTES;
    }
    const uint32_t off = (uint32_t)row * 128u + (uint32_t)j * 16u;
    cp16(dstBase + swz(off), src + k0 + j * 8);
  }
}

// Load one ks-slice of fragments.
__device__ __forceinline__ void load_frags(uint32_t sA, uint32_t sB, int ks,
                                           int warp_m, int warp_n, int a_row,
                                           int a_kb, int b_row, int b_kb,
                                           uint32_t af[4][4], uint32_t bf[8][2]) {
#pragma unroll
  for (int mf = 0; mf < 4; mf++) {
    const uint32_t off =
        (uint32_t)(warp_m + mf * 16 + a_row) * 128u + ks * 32 + a_kb;
    LDM_X4(af[mf][0], af[mf][1], af[mf][2], af[mf][3], sA + swz(off));
  }
#pragma unroll
  for (int nf2 = 0; nf2 < 4; nf2++) {
    const uint32_t off =
        (uint32_t)(warp_n + nf2 * 16 + b_row) * 128u + ks * 32 + b_kb;
    uint32_t t0, t1, t2, t3;
    LDM_X4(t0, t1, t2, t3, sB + swz(off));
    bf[nf2 * 2][0] = t0;
    bf[nf2 * 2][1] = t1;
    bf[nf2 * 2 + 1][0] = t2;
    bf[nf2 * 2 + 1][1] = t3;
  }
}

// ---------------------------------------------------------------------------
// GEMM core (round-8 mainloop): C[m,n] = act( sum_k A[m,k] * W[n,k] ).
// outMode: 0 = float store, 1 = sigmoid + half store, 2 = half store.
// ---------------------------------------------------------------------------
__device__ __forceinline__ void gemm_core(const __half* __restrict__ A,
                                          const __half* __restrict__ W,
                                          void* __restrict__ C, int outMode,
                                          int mBase, int nBase, uint32_t sb,
                                          int tid) {
  const int wid = tid >> 5;
  const int lid = tid & 31;
  const int warp_m = (wid & 1) * 64;
  const int warp_n = (wid >> 1) * 64;

  float acc[4][8][4];
#pragma unroll
  for (int a = 0; a < 4; a++)
#pragma unroll
    for (int b = 0; b < 8; b++)
#pragma unroll
      for (int c = 0; c < 4; c++) acc[a][b][c] = 0.f;

  stage_fill(sb, A, W, mBase, nBase, 0, tid);
  CP_COMMIT();
  stage_fill(sb + STAGE_BYTES, A, W, mBase, nBase, BKH, tid);
  CP_COMMIT();

  const int am = lid >> 3;
  const int a_row = ((am & 1) * 8) + (lid & 7);
  const int a_kb = (am >> 1) * 16;
  const int b_row = ((am >> 1) * 8) + (lid & 7);
  const int b_kb = (am & 1) * 16;

  uint32_t af[2][4][4];
  uint32_t bf[2][8][2];

  uint32_t curSlot = sb, fillSlot = sb + 2 * STAGE_BYTES;
  for (int i = 0; i < KSTAGES; i++) {
    CP_WAIT1();
    __syncthreads();
    if (i + 2 < KSTAGES)
      stage_fill(fillSlot, A, W, mBase, nBase, (i + 2) * BKH, tid);
    CP_COMMIT();

    const uint32_t sA = curSlot;
    const uint32_t sB = curSlot + A_BYTES;

    load_frags(sA, sB, 0, warp_m, warp_n, a_row, a_kb, b_row, b_kb, af[0],
               bf[0]);
#pragma unroll
    for (int ks = 0; ks < 4; ks++) {
      const int p = ks & 1;
      if (ks < 3)
        load_frags(sA, sB, ks + 1, warp_m, warp_n, a_row, a_kb, b_row, b_kb,
                   af[1 - p], bf[1 - p]);
#pragma unroll
      for (int mf = 0; mf < 4; mf++)
#pragma unroll
        for (int nf = 0; nf < 8; nf++)
          MMA16816(acc[mf][nf], af[p][mf], bf[p][nf]);
    }
    const uint32_t old = curSlot;
    curSlot = (curSlot == sb + 2 * STAGE_BYTES) ? sb : curSlot + STAGE_BYTES;
    fillSlot = old;
  }

  // Epilogue.
#pragma unroll
  for (int mf = 0; mf < 4; mf++) {
    const int r0 = mBase + warp_m + mf * 16 + (lid >> 2);
#pragma unroll
    for (int nf = 0; nf < 8; nf++) {
      const int cc = nBase + warp_n + nf * 8 + (lid & 3) * 2;
      float v[4] = {acc[mf][nf][0], acc[mf][nf][1], acc[mf][nf][2],
                    acc[mf][nf][3]};
      if (outMode == 1) {
#pragma unroll
        for (int q = 0; q < 4; q++) v[q] = 1.f / (1.f + expf(-v[q]));
      }
      if (outMode == 0) {
        float* Cf = (float*)C;
        *(float2*)&Cf[(size_t)r0 * kD + cc] = make_float2(v[0], v[1]);
        *(float2*)&Cf[(size_t)(r0 + 8) * kD + cc] = make_float2(v[2], v[3]);
      } else {
        __half* Ch = (__half*)C;
        *(__half2*)&Ch[(size_t)r0 * kD + cc] = __floats2half2_rn(v[0], v[1]);
        *(__half2*)&Ch[(size_t)(r0 + 8) * kD + cc] =
            __floats2half2_rn(v[2], v[3]);
      }
    }
  }
}

// Scan pass A body (128 threads, 2 channels each -> 256 channels per block).
__device__ __forceinline__ void scan_partial_body(const float* __restrict__ td,
                                                  int x, int b, int c, int tid) {
  const int e = (x * 128 + tid) * 2;
  const float dec0 = expf(td[e]);
  const float dec1 = expf(td[e + 1]);
  float n0 = 0.f, n1 = 0.f, d0 = 0.f, d1 = 0.f;
  size_t base = (size_t)(b * kS + c * kCLen) * kD + e;
#pragma unroll 4
  for (int i = 0; i < kCLen; i++) {
    const float2 kk = __ldcs((const float2*)&g_k[base]);
    const float2 ww = __ldcs((const float2*)&g_w[base]);
    const __half2 vh = __ldcs((const __half2*)&g_vh[base]);
    const float2 vf = __half22float2(vh);
    const float ew0 = expf(kk.x - expf(ww.x));
    const float ew1 = expf(kk.y - expf(ww.y));
    n0 = fmaf(dec0, n0, ew0 * vf.x);
    n1 = fmaf(dec1, n1, ew1 * vf.y);
    d0 = fmaf(dec0, d0, ew0);
    d1 = fmaf(dec1, d1, ew1);
    base += kD;
  }
  const size_t ci = (size_t)(c * kB + b) * kD + e;
  *(float2*)&g_cnum[ci] = make_float2(n0, n1);
  *(float2*)&g_cden[ci] = make_float2(d0, d1);
}

struct Proj3 {
  const __half* W[3];
  void* C[3];
};

// Fused 3-projection GEMM (w,k,v): widx 0=w(f32) 1=k(f32) 2=v(half)
__global__ __launch_bounds__(NTHR, 2) void gemm_fused3(
    const __half* __restrict__ A, Proj3 p) {
  extern __shared__ char smem[];
  const uint32_t sb = smem_u32(smem);
  const int widx = blockIdx.x / NTILES;
  const int nb = blockIdx.x - widx * NTILES;
  const int mode = (widx == 2) ? 2 : 0;
  gemm_core(A, p.W[widx], p.C[widx], mode, blockIdx.y * BM, nb * BN, sb,
            threadIdx.x);
}

// Hybrid: even blocks = r-projection GEMM tile; odd blocks = scan_partial.
// Co-resident on SMs: tensor-bound GEMM + HBM-bound scan overlap.
__global__ __launch_bounds__(NTHR, 2) void hybrid_r_scan(
    const __half* __restrict__ A, const __half* __restrict__ Wr,
    __half* __restrict__ Crh, const float* __restrict__ td) {
  extern __shared__ char smem[];
  const int t = blockIdx.x >> 1;  // 0..2047
  if ((blockIdx.x & 1) == 0) {
    const int nb = t & (NTILES - 1);
    const int mb = t >> 4;
    gemm_core(A, Wr, Crh, 1, mb * BM, nb * BN, smem_u32(smem), threadIdx.x);
  } else {
    // t = ((c*kB)+b)*8 + x, x in 0..7, b in 0..3, c in 0..63
    const int x = t & 7;
    const int b = (t >> 3) & 3;
    const int c = t >> 5;
    scan_partial_body(td, x, b, c, threadIdx.x);
  }
}

// Output projection (float out).
__global__ __launch_bounds__(NTHR, 2) void gemm_one(
    const __half* __restrict__ A, const __half* __restrict__ W,
    float* __restrict__ C) {
  extern __shared__ char smem[];
  const uint32_t sb = smem_u32(smem);
  gemm_core(A, W, C, 0, blockIdx.y * BM, blockIdx.x * BN, sb, threadIdx.x);
}

// ---------------------- fp32 -> fp16 (x + 5 weights) -----------------------
struct Ptr5 { const float* p[5]; };

__global__ __launch_bounds__(256) void cvt_all(const float* __restrict__ x,
                                               Ptr5 wsrc,
                                               __half2* __restrict__ xh,
                                               __half2* __restrict__ wh) {
  const int z = blockIdx.z;
  const float* s;
  __half2* d;
  int n4;
  if (z == 0) {
    s = x; d = xh; n4 = kM * kD / 4;
  } else {
    s = wsrc.p[z - 1];
    d = wh + (size_t)(z - 1) * (kD * kD / 2);
    n4 = kD * kD / 4;
  }
  int i = blockIdx.x * blockDim.x + threadIdx.x;
  const int stride = gridDim.x * blockDim.x;
  for (; i < n4; i += stride) {
    const float4 v = ((const float4*)s)[i];
    d[2 * i] = __floats2half2_rn(v.x, v.y);
    d[2 * i + 1] = __floats2half2_rn(v.z, v.w);
  }
}

// ------------------------------- scan kernels ------------------------------
// Pass B: cross-chunk carry via warp Kogge-Stone. One warp per (b,e) channel.
__global__ __launch_bounds__(256) void scan_carry(const float* __restrict__ td,
                                                  float* __restrict__ out) {
  const int gw = (blockIdx.x * 256 + threadIdx.x) >> 5;  // 0..8191
  const int lane = threadIdx.x & 31;
  const int b = gw >> 11;
  const int e = gw & (kD - 1);
  const float decL = expf(td[e] * (float)kCLen);

  const int c0 = 2 * lane;
  const size_t ci0 = (size_t)(c0 * kB + b) * kD + e;
  const size_t ci1 = (size_t)((c0 + 1) * kB + b) * kD + e;
  const float pn0 = g_cnum[ci0], pd0 = g_cden[ci0];
  const float pn1 = g_cnum[ci1], pd1 = g_cden[ci1];

  float vn = fmaf(decL, pn0, pn1);
  float vd = fmaf(decL, pd0, pd1);

  float coef = decL * decL;
#pragma unroll
  for (int off = 1; off < 32; off <<= 1) {
    const float un = __shfl_up_sync(0xffffffffu, vn, off);
    const float ud = __shfl_up_sync(0xffffffffu, vd, off);
    if (lane >= off) {
      vn = fmaf(coef, un, vn);
      vd = fmaf(coef, ud, vd);
    }
    coef *= coef;
  }
  float en = __shfl_up_sync(0xffffffffu, vn, 1);
  float ed = __shfl_up_sync(0xffffffffu, vd, 1);
  if (lane == 0) { en = 0.f; ed = 0.f; }
  g_inum[ci0] = en;
  g_iden[ci0] = ed;
  g_inum[ci1] = fmaf(decL, en, pn0);
  g_iden[ci1] = fmaf(decL, ed, pd0);

  if (lane == 31) {
    float* fs = out + (size_t)kM * kD;
    fs[b * 2 * kD + e] = vn;
    fs[b * 2 * kD + kD + e] = vd;
  }
}

// Pass C: rescan with carry-in, y = r*wkv as fp16. 2 channels per thread.
__global__ __launch_bounds__(256) void scan_final(const float* __restrict__ td) {
  const int e = (blockIdx.x * 256 + threadIdx.x) * 2;
  const int b = blockIdx.y;
  const int c = blockIdx.z;
  const float dec0 = expf(td[e]);
  const float dec1 = expf(td[e + 1]);
  const size_t ci = (size_t)(c * kB + b) * kD + e;
  const float2 ni = *(const float2*)&g_inum[ci];
  const float2 di = *(const float2*)&g_iden[ci];
  float n0 = ni.x, n1 = ni.y, d0 = di.x, d1 = di.y;
  size_t base = (size_t)(b * kS + c * kCLen) * kD + e;
#pragma unroll 4
  for (int i = 0; i < kCLen; i++) {
    const float2 kk = __ldcs((const float2*)&g_k[base]);
    const float2 ww = __ldcs((const float2*)&g_w[base]);
    const __half2 vh = __ldcs((const __half2*)&g_vh[base]);
    const __half2 rh = __ldcs((const __half2*)&g_rh[base]);
    const float2 vf = __half22float2(vh);
    const float2 rf = __half22float2(rh);
    const float ew0 = expf(kk.x - expf(ww.x));
    const float ew1 = expf(kk.y - expf(ww.y));
    n0 = fmaf(dec0, n0, ew0 * vf.x);
    n1 = fmaf(dec1, n1, ew1 * vf.y);
    d0 = fmaf(dec0, d0, ew0);
    d1 = fmaf(dec1, d1, ew1);
    const float y0 = rf.x * (n0 / (d0 + 1e-8f));
    const float y1 = rf.y * (n1 / (d1 + 1e-8f));
    __stcs((__half2*)&g_yh[base], __floats2half2_rn(y0, y1));
    base += kD;
  }
}

// ---------------------------------------------------------------------------
extern "C" void kernel_launch(void* const* d_in, const int* in_sizes, int n_in,
                              void* d_out, int out_size) {
  const float* x = (const float*)d_in[0];
  Ptr5 wp;
  for (int i = 0; i < 5; i++) wp.p[i] = (const float*)d_in[i + 1];
  const float* td = (const float*)d_in[6];
  float* out = (float*)d_out;

  float *pw, *pk;
  cudaGetSymbolAddress((void**)&pw, g_w);
  cudaGetSymbolAddress((void**)&pk, g_k);
  __half *prh, *pvh, *xh, *yh, *wh;
  cudaGetSymbolAddress((void**)&prh, g_rh);
  cudaGetSymbolAddress((void**)&pvh, g_vh);
  cudaGetSymbolAddress((void**)&xh, g_xh);
  cudaGetSymbolAddress((void**)&yh, g_yh);
  cudaGetSymbolAddress((void**)&wh, g_wh);

  cudaFuncSetAttribute(gemm_fused3, cudaFuncAttributeMaxDynamicSharedMemorySize,
                       SMEM_BYTES);
  cudaFuncSetAttribute(hybrid_r_scan,
                       cudaFuncAttributeMaxDynamicSharedMemorySize, SMEM_BYTES);
  cudaFuncSetAttribute(gemm_one, cudaFuncAttributeMaxDynamicSharedMemorySize,
                       SMEM_BYTES);

  cvt_all<<<dim3(2048, 1, 6), 256>>>(x, wp, (__half2*)xh, (__half2*)wh);

  const __half* Wr = wh + 0 * (size_t)kD * kD;
  Proj3 p;
  p.W[0] = wh + 1 * (size_t)kD * kD;  // Ww
  p.W[1] = wh + 2 * (size_t)kD * kD;  // Wk
  p.W[2] = wh + 3 * (size_t)kD * kD;  // Wv
  p.C[0] = pw; p.C[1] = pk; p.C[2] = pvh;
  const __half* Wo = wh + 4 * (size_t)kD * kD;

  // w,k,v projections
  gemm_fused3<<<dim3(3 * NTILES, kM / BM), NTHR, SMEM_BYTES>>>(xh, p);
  // r projection co-scheduled with scan pass A (independent workloads)
  hybrid_r_scan<<<4096, NTHR, SMEM_BYTES>>>(xh, Wr, prh, td);

  scan_carry<<<kB * kD / 8, 256>>>(td, out);  // one warp per channel
  scan_final<<<dim3(kD / 512, kB, kChunks), 256>>>(td);

  gemm_one<<<dim3(NTILES, kM / BM), NTHR, SMEM_BYTES>>>(yh, Wo, out);
}

// round 11
// speedup vs baseline: 1.0350x; 1.0350x over previous
#include <cuda_runtime.h>
#include <cuda_fp16.h>
#include <math.h>
#include <stdint.h>

// ---------------------------------------------------------------------------
// TimeMix (RWKV-style): B=4, S=4096, D=2048 — fp16 mma.sync (round-8 base),
// 4-channel vectorized streaming scans, streaming epilogue stores.
// ---------------------------------------------------------------------------

namespace {
constexpr int kB = 4;
constexpr int kS = 4096;
constexpr int kD = 2048;
constexpr int kM = kB * kS;          // 16384
constexpr int kChunks = 64;
constexpr int kCLen = kS / kChunks;  // 64

constexpr int BM = 128, BN = 128, BKH = 64;  // BKH halves = 128 B rows
constexpr int NTHR = 128;                    // 4 warps, 2x2 of 64x64
constexpr int KSTAGES = kD / BKH;            // 32
constexpr uint32_t A_BYTES = BM * 128;       // 16384
constexpr uint32_t STAGE_BYTES = 2 * A_BYTES;     // 32768
constexpr uint32_t SMEM_BYTES = 3 * STAGE_BYTES;  // 98304
constexpr int NTILES = kD / BN;              // 16
}  // namespace

// Scratch (device globals; allocation APIs forbidden)
__device__ float g_w[kM * kD];
__device__ float g_k[kM * kD];
__device__ __align__(16) __half g_rh[kM * kD];
__device__ __align__(16) __half g_vh[kM * kD];
__device__ float g_cnum[kChunks * kB * kD];
__device__ float g_cden[kChunks * kB * kD];
__device__ float g_inum[kChunks * kB * kD];
__device__ float g_iden[kChunks * kB * kD];
__device__ __align__(16) __half g_xh[kM * kD];
__device__ __align__(16) __half g_yh[kM * kD];
__device__ __align__(16) __half g_wh[5][kD * kD];

// ------------------------------- asm helpers -------------------------------
__device__ __forceinline__ uint32_t smem_u32(const void* p) {
  uint32_t a;
  asm("{ .reg .u64 t; cvta.to.shared.u64 t, %1; cvt.u32.u64 %0, t; }"
      : "=r"(a) : "l"(p));
  return a;
}
__device__ __forceinline__ void cp16(uint32_t dst, const void* src) {
  asm volatile("cp.async.cg.shared.global [%0], [%1], 16;" :: "r"(dst), "l"(src));
}
#define CP_COMMIT() asm volatile("cp.async.commit_group;" ::: "memory")
#define CP_WAIT1() asm volatile("cp.async.wait_group 1;" ::: "memory")

#define LDM_X4(r0, r1, r2, r3, addr)                                           \
  asm volatile("ldmatrix.sync.aligned.m8n8.x4.shared.b16 {%0,%1,%2,%3}, [%4];" \
               : "=r"(r0), "=r"(r1), "=r"(r2), "=r"(r3) : "r"(addr))

#define MMA16816(d, a, b)                                                   \
  asm volatile(                                                             \
      "mma.sync.aligned.m16n8k16.row.col.f32.f16.f16.f32 "                  \
      "{%0,%1,%2,%3}, {%4,%5,%6,%7}, {%8,%9}, {%0,%1,%2,%3};"               \
      : "+f"(d[0]), "+f"(d[1]), "+f"(d[2]), "+f"(d[3])                      \
      : "r"(a[0]), "r"(a[1]), "r"(a[2]), "r"(a[3]), "r"(b[0]), "r"(b[1]))

__device__ __forceinline__ uint32_t swz(uint32_t off) {
  return off ^ ((off >> 3) & 0x70);
}

// Fill one stage: A tile 128 x 128B, B tile 128 x 128B. K-major, SW128.
__device__ __forceinline__ void stage_fill(uint32_t slotbase, const __half* A,
                                           const __half* W, int mBase,
                                           int nBase, int k0, int tid) {
#pragma unroll
  for (int t = 0; t < 16; t++) {
    const int idx = tid + t * NTHR;     // 0..2047
    const int row = (idx & 1023) >> 3;  // 0..127
    const int j = idx & 7;              // 16B chunk in row
    const __half* src;
    uint32_t dstBase;
    if (idx < 1024) {
      src = A + (size_t)(mBase + row) * kD;
      dstBase = slotbase;
    } else {
      src = W + (size_t)(nBase + row) * kD;
      dstBase = slotbase + A_BYTES;
    }
    const uint32_t off = (uint32_t)row * 128u + (uint32_t)j * 16u;
    cp16(dstBase + swz(off), src + k0 + j * 8);
  }
}

// Load one ks-slice of fragments.
__device__ __forceinline__ void load_frags(uint32_t sA, uint32_t sB, int ks,
                                           int warp_m, int warp_n, int a_row,
                                           int a_kb, int b_row, int b_kb,
                                           uint32_t af[4][4], uint32_t bf[8][2]) {
#pragma unroll
  for (int mf = 0; mf < 4; mf++) {
    const uint32_t off =
        (uint32_t)(warp_m + mf * 16 + a_row) * 128u + ks * 32 + a_kb;
    LDM_X4(af[mf][0], af[mf][1], af[mf][2], af[mf][3], sA + swz(off));
  }
#pragma unroll
  for (int nf2 = 0; nf2 < 4; nf2++) {
    const uint32_t off =
        (uint32_t)(warp_n + nf2 * 16 + b_row) * 128u + ks * 32 + b_kb;
    uint32_t t0, t1, t2, t3;
    LDM_X4(t0, t1, t2, t3, sB + swz(off));
    bf[nf2 * 2][0] = t0;
    bf[nf2 * 2][1] = t1;
    bf[nf2 * 2 + 1][0] = t2;
    bf[nf2 * 2 + 1][1] = t3;
  }
}

// ---------------------------------------------------------------------------
// GEMM core (round-8 mainloop): C[m,n] = act( sum_k A[m,k] * W[n,k] ).
// outMode: 0 = float store, 1 = sigmoid + half store, 2 = half store.
// ---------------------------------------------------------------------------
__device__ __forceinline__ void gemm_core(const __half* __restrict__ A,
                                          const __half* __restrict__ W,
                                          void* __restrict__ C, int outMode,
                                          int mBase, int nBase, uint32_t sb,
                                          int tid) {
  const int wid = tid >> 5;
  const int lid = tid & 31;
  const int warp_m = (wid & 1) * 64;
  const int warp_n = (wid >> 1) * 64;

  float acc[4][8][4];
#pragma unroll
  for (int a = 0; a < 4; a++)
#pragma unroll
    for (int b = 0; b < 8; b++)
#pragma unroll
      for (int c = 0; c < 4; c++) acc[a][b][c] = 0.f;

  stage_fill(sb, A, W, mBase, nBase, 0, tid);
  CP_COMMIT();
  stage_fill(sb + STAGE_BYTES, A, W, mBase, nBase, BKH, tid);
  CP_COMMIT();

  const int am = lid >> 3;
  const int a_row = ((am & 1) * 8) + (lid & 7);
  const int a_kb = (am >> 1) * 16;
  const int b_row = ((am >> 1) * 8) + (lid & 7);
  const int b_kb = (am & 1) * 16;

  uint32_t af[2][4][4];
  uint32_t bf[2][8][2];

  uint32_t curSlot = sb, fillSlot = sb + 2 * STAGE_BYTES;
  for (int i = 0; i < KSTAGES; i++) {
    CP_WAIT1();
    __syncthreads();
    if (i + 2 < KSTAGES)
      stage_fill(fillSlot, A, W, mBase, nBase, (i + 2) * BKH, tid);
    CP_COMMIT();

    const uint32_t sA = curSlot;
    const uint32_t sB = curSlot + A_BYTES;

    load_frags(sA, sB, 0, warp_m, warp_n, a_row, a_kb, b_row, b_kb, af[0],
               bf[0]);
#pragma unroll
    for (int ks = 0; ks < 4; ks++) {
      const int p = ks & 1;
      if (ks < 3)
        load_frags(sA, sB, ks + 1, warp_m, warp_n, a_row, a_kb, b_row, b_kb,
                   af[1 - p], bf[1 - p]);
#pragma unroll
      for (int mf = 0; mf < 4; mf++)
#pragma unroll
        for (int nf = 0; nf < 8; nf++)
          MMA16816(acc[mf][nf], af[p][mf], bf[p][nf]);
    }
    const uint32_t old = curSlot;
    curSlot = (curSlot == sb + 2 * STAGE_BYTES) ? sb : curSlot + STAGE_BYTES;
    fillSlot = old;
  }

  // Epilogue: streaming stores (outputs are consumed from DRAM later; keep
  // weight working set in L2 instead).
#pragma unroll
  for (int mf = 0; mf < 4; mf++) {
    const int r0 = mBase + warp_m + mf * 16 + (lid >> 2);
#pragma unroll
    for (int nf = 0; nf < 8; nf++) {
      const int cc = nBase + warp_n + nf * 8 + (lid & 3) * 2;
      float v[4] = {acc[mf][nf][0], acc[mf][nf][1], acc[mf][nf][2],
                    acc[mf][nf][3]};
      if (outMode == 1) {
#pragma unroll
        for (int q = 0; q < 4; q++) v[q] = 1.f / (1.f + expf(-v[q]));
      }
      if (outMode == 0) {
        float* Cf = (float*)C;
        __stcs((float2*)&Cf[(size_t)r0 * kD + cc], make_float2(v[0], v[1]));
        __stcs((float2*)&Cf[(size_t)(r0 + 8) * kD + cc],
               make_float2(v[2], v[3]));
      } else {
        __half* Ch = (__half*)C;
        const __half2 h0 = __floats2half2_rn(v[0], v[1]);
        const __half2 h1 = __floats2half2_rn(v[2], v[3]);
        __stcs((__half2*)&Ch[(size_t)r0 * kD + cc], h0);
        __stcs((__half2*)&Ch[(size_t)(r0 + 8) * kD + cc], h1);
      }
    }
  }
}

struct Proj4 {
  const __half* W[4];
  void* C[4];
};

// Fused 4-projection GEMM: widx 0=r(sigmoid,half) 1=w(f32) 2=k(f32) 3=v(half)
__global__ __launch_bounds__(NTHR, 2) void gemm_fused(
    const __half* __restrict__ A, Proj4 p) {
  extern __shared__ char smem[];
  const uint32_t sb = smem_u32(smem);
  const int widx = blockIdx.x / NTILES;
  const int nb = blockIdx.x - widx * NTILES;
  const int mode = (widx == 0) ? 1 : (widx == 3 ? 2 : 0);
  gemm_core(A, p.W[widx], p.C[widx], mode, blockIdx.y * BM, nb * BN, sb,
            threadIdx.x);
}

// Output projection (float out).
__global__ __launch_bounds__(NTHR, 2) void gemm_one(
    const __half* __restrict__ A, const __half* __restrict__ W,
    float* __restrict__ C) {
  extern __shared__ char smem[];
  const uint32_t sb = smem_u32(smem);
  gemm_core(A, W, C, 0, blockIdx.y * BM, blockIdx.x * BN, sb, threadIdx.x);
}

// ---------------------- fp32 -> fp16 (x + 5 weights) -----------------------
struct Ptr5 { const float* p[5]; };

__global__ __launch_bounds__(256) void cvt_all(const float* __restrict__ x,
                                               Ptr5 wsrc,
                                               __half2* __restrict__ xh,
                                               __half2* __restrict__ wh) {
  const int z = blockIdx.z;
  const float* s;
  __half2* d;
  int n4;
  if (z == 0) {
    s = x; d = xh; n4 = kM * kD / 4;
  } else {
    s = wsrc.p[z - 1];
    d = wh + (size_t)(z - 1) * (kD * kD / 2);
    n4 = kD * kD / 4;
  }
  int i = blockIdx.x * blockDim.x + threadIdx.x;
  const int stride = gridDim.x * blockDim.x;
  for (; i < n4; i += stride) {
    const float4 v = ((const float4*)s)[i];
    d[2 * i] = __floats2half2_rn(v.x, v.y);
    d[2 * i + 1] = __floats2half2_rn(v.z, v.w);
  }
}

// ------------------------------- scan kernels ------------------------------
// Pass A: per-chunk local scan, 4 channels per thread, streaming 16B loads.
__global__ __launch_bounds__(256) void scan_partial(const float* __restrict__ td) {
  const int e = (blockIdx.x * 256 + threadIdx.x) * 4;
  const int b = blockIdx.y;
  const int c = blockIdx.z;
  float dec[4], n[4] = {0.f, 0.f, 0.f, 0.f}, d[4] = {0.f, 0.f, 0.f, 0.f};
#pragma unroll
  for (int q = 0; q < 4; q++) dec[q] = expf(td[e + q]);
  size_t base = (size_t)(b * kS + c * kCLen) * kD + e;
#pragma unroll 2
  for (int i = 0; i < kCLen; i++) {
    const float4 kk = __ldcs((const float4*)&g_k[base]);
    const float4 ww = __ldcs((const float4*)&g_w[base]);
    const uint2 vu = __ldcs((const uint2*)&g_vh[base]);
    const float2 v01 = __half22float2(*(const __half2*)&vu.x);
    const float2 v23 = __half22float2(*(const __half2*)&vu.y);
    const float kv[4] = {kk.x, kk.y, kk.z, kk.w};
    const float wv[4] = {ww.x, ww.y, ww.z, ww.w};
    const float vv[4] = {v01.x, v01.y, v23.x, v23.y};
#pragma unroll
    for (int q = 0; q < 4; q++) {
      const float ew = expf(kv[q] - expf(wv[q]));
      n[q] = fmaf(dec[q], n[q], ew * vv[q]);
      d[q] = fmaf(dec[q], d[q], ew);
    }
    base += kD;
  }
  const size_t ci = (size_t)(c * kB + b) * kD + e;
  *(float4*)&g_cnum[ci] = make_float4(n[0], n[1], n[2], n[3]);
  *(float4*)&g_cden[ci] = make_float4(d[0], d[1], d[2], d[3]);
}

// Pass B: cross-chunk carry via warp Kogge-Stone. One warp per (b,e) channel.
__global__ __launch_bounds__(256) void scan_carry(const float* __restrict__ td,
                                                  float* __restrict__ out) {
  const int gw = (blockIdx.x * 256 + threadIdx.x) >> 5;  // 0..8191
  const int lane = threadIdx.x & 31;
  const int b = gw >> 11;
  const int e = gw & (kD - 1);
  const float decL = expf(td[e] * (float)kCLen);

  const int c0 = 2 * lane;
  const size_t ci0 = (size_t)(c0 * kB + b) * kD + e;
  const size_t ci1 = (size_t)((c0 + 1) * kB + b) * kD + e;
  const float pn0 = g_cnum[ci0], pd0 = g_cden[ci0];
  const float pn1 = g_cnum[ci1], pd1 = g_cden[ci1];

  float vn = fmaf(decL, pn0, pn1);
  float vd = fmaf(decL, pd0, pd1);

  float coef = decL * decL;
#pragma unroll
  for (int off = 1; off < 32; off <<= 1) {
    const float un = __shfl_up_sync(0xffffffffu, vn, off);
    const float ud = __shfl_up_sync(0xffffffffu, vd, off);
    if (lane >= off) {
      vn = fmaf(coef, un, vn);
      vd = fmaf(coef, ud, vd);
    }
    coef *= coef;
  }
  float en = __shfl_up_sync(0xffffffffu, vn, 1);
  float ed = __shfl_up_sync(0xffffffffu, vd, 1);
  if (lane == 0) { en = 0.f; ed = 0.f; }
  g_inum[ci0] = en;
  g_iden[ci0] = ed;
  g_inum[ci1] = fmaf(decL, en, pn0);
  g_iden[ci1] = fmaf(decL, ed, pd0);

  if (lane == 31) {
    float* fs = out + (size_t)kM * kD;
    fs[b * 2 * kD + e] = vn;
    fs[b * 2 * kD + kD + e] = vd;
  }
}

// Pass C: rescan with carry-in, y = r*wkv as fp16. 4 channels per thread.
__global__ __launch_bounds__(256) void scan_final(const float* __restrict__ td) {
  const int e = (blockIdx.x * 256 + threadIdx.x) * 4;
  const int b = blockIdx.y;
  const int c = blockIdx.z;
  float dec[4];
#pragma unroll
  for (int q = 0; q < 4; q++) dec[q] = expf(td[e + q]);
  const size_t ci = (size_t)(c * kB + b) * kD + e;
  const float4 ni = *(const float4*)&g_inum[ci];
  const float4 di = *(const float4*)&g_iden[ci];
  float n[4] = {ni.x, ni.y, ni.z, ni.w};
  float d[4] = {di.x, di.y, di.z, di.w};
  size_t base = (size_t)(b * kS + c * kCLen) * kD + e;
#pragma unroll 2
  for (int i = 0; i < kCLen; i++) {
    const float4 kk = __ldcs((const float4*)&g_k[base]);
    const float4 ww = __ldcs((const float4*)&g_w[base]);
    const uint2 vu = __ldcs((const uint2*)&g_vh[base]);
    const uint2 ru = __ldcs((const uint2*)&g_rh[base]);
    const float2 v01 = __half22float2(*(const __half2*)&vu.x);
    const float2 v23 = __half22float2(*(const __half2*)&vu.y);
    const float2 r01 = __half22float2(*(const __half2*)&ru.x);
    const float2 r23 = __half22float2(*(const __half2*)&ru.y);
    const float kv[4] = {kk.x, kk.y, kk.z, kk.w};
    const float wv[4] = {ww.x, ww.y, ww.z, ww.w};
    const float vv[4] = {v01.x, v01.y, v23.x, v23.y};
    const float rv[4] = {r01.x, r01.y, r23.x, r23.y};
    float y[4];
#pragma unroll
    for (int q = 0; q < 4; q++) {
      const float ew = expf(kv[q] - expf(wv[q]));
      n[q] = fmaf(dec[q], n[q], ew * vv[q]);
      d[q] = fmaf(dec[q], d[q], ew);
      y[q] = rv[q] * (n[q] / (d[q] + 1e-8f));
    }
    uint2 yo;
    const __half2 y01 = __floats2half2_rn(y[0], y[1]);
    const __half2 y23 = __floats2half2_rn(y[2], y[3]);
    yo.x = *(const uint32_t*)&y01;
    yo.y = *(const uint32_t*)&y23;
    __stcs((uint2*)&g_yh[base], yo);
    base += kD;
  }
}

// ---------------------------------------------------------------------------
extern "C" void kernel_launch(void* const* d_in, const int* in_sizes, int n_in,
                              void* d_out, int out_size) {
  const float* x = (const float*)d_in[0];
  Ptr5 wp;
  for (int i = 0; i < 5; i++) wp.p[i] = (const float*)d_in[i + 1];
  const float* td = (const float*)d_in[6];
  float* out = (float*)d_out;

  float *pw, *pk;
  cudaGetSymbolAddress((void**)&pw, g_w);
  cudaGetSymbolAddress((void**)&pk, g_k);
  __half *prh, *pvh, *xh, *yh, *wh;
  cudaGetSymbolAddress((void**)&prh, g_rh);
  cudaGetSymbolAddress((void**)&pvh, g_vh);
  cudaGetSymbolAddress((void**)&xh, g_xh);
  cudaGetSymbolAddress((void**)&yh, g_yh);
  cudaGetSymbolAddress((void**)&wh, g_wh);

  cudaFuncSetAttribute(gemm_fused, cudaFuncAttributeMaxDynamicSharedMemorySize,
                       SMEM_BYTES);
  cudaFuncSetAttribute(gemm_one, cudaFuncAttributeMaxDynamicSharedMemorySize,
                       SMEM_BYTES);

  cvt_all<<<dim3(2048, 1, 6), 256>>>(x, wp, (__half2*)xh, (__half2*)wh);

  Proj4 p;
  p.W[0] = wh + 0 * (size_t)kD * kD;  // Wr
  p.W[1] = wh + 1 * (size_t)kD * kD;  // Ww
  p.W[2] = wh + 2 * (size_t)kD * kD;  // Wk
  p.W[3] = wh + 3 * (size_t)kD * kD;  // Wv
  p.C[0] = prh; p.C[1] = pw; p.C[2] = pk; p.C[3] = pvh;
  const __half* Wo = wh + 4 * (size_t)kD * kD;

  gemm_fused<<<dim3(4 * NTILES, kM / BM), NTHR, SMEM_BYTES>>>(xh, p);

  dim3 gs(kD / 1024, kB, kChunks);  // 4 channels per thread
  scan_partial<<<gs, 256>>>(td);
  scan_carry<<<kB * kD / 8, 256>>>(td, out);  // one warp per channel
  scan_final<<<gs, 256>>>(td);

  gemm_one<<<dim3(NTILES, kM / BM), NTHR, SMEM_BYTES>>>(yh, Wo, out);
}